// round 15
// baseline (speedup 1.0000x reference)
#include <cuda_runtime.h>
#include <cuda_bf16.h>
#include <math_constants.h>
#include <cstdint>

// ===========================================================================
// VectorQuantizer: x (64,1024,256) f32, codebook vectors (256,4096) f32.
// Outputs (flattened f32): [0,N*D) quantized_st; [N*D] dict_loss; [N*D+1]
// commitment_loss; [N*D+2, +N) indices as float.
//
// Phase 1: bf16 HMMA (mma.sync m16n8k16 + ldmatrix, family-wide PTX) approx
//          scores; per-row running min + candidate collect (<= runmin + TAU).
// Phase 2 (FUSED into the same kernel as a per-CTA tail): exact fp32 rescore
//          with the reference rounding chain s = fl(fl(A - 2*dot) + C);
//          A computed inline with the bit-exact XLA warp-reduce order;
//          gather / straight-through output / fp64 loss partials.
//          The tail of one CTA overlaps the co-resident CTA's HMMA stream.
// ===========================================================================

#define DDIM 256
#define KDIM 4096
#define MAXN 65536
#define CAP  32
#define TAU  2.5e-3f

__device__ float         g_v2[KDIM];
__device__ double        g_partials[256];
__device__ float         g_vT[KDIM * DDIM];
__device__ __nv_bfloat16 g_vTh[KDIM * DDIM];
__device__ int           g_candcnt[MAXN];
__device__ int           g_cand[MAXN * CAP];

// ---------------------------------------------------------------------------
__device__ __forceinline__ void mma_bf16(float* d, const uint32_t* a,
                                         const uint32_t* b) {
    asm volatile(
        "mma.sync.aligned.m16n8k16.row.col.f32.bf16.bf16.f32 "
        "{%0,%1,%2,%3}, {%4,%5,%6,%7}, {%8,%9}, {%0,%1,%2,%3};"
        : "+f"(d[0]), "+f"(d[1]), "+f"(d[2]), "+f"(d[3])
        : "r"(a[0]), "r"(a[1]), "r"(a[2]), "r"(a[3]), "r"(b[0]), "r"(b[1]));
}
__device__ __forceinline__ void ldm_x4(uint32_t* r, uint32_t addr) {
    asm volatile("ldmatrix.sync.aligned.m8n8.x4.shared.b16 {%0,%1,%2,%3}, [%4];"
        : "=r"(r[0]), "=r"(r[1]), "=r"(r[2]), "=r"(r[3]) : "r"(addr));
}

// ---------------------------------------------------------------------------
// Kernel A1: C_k = ||v_k||^2 (fp64); zero loss partials + cand counts
// ---------------------------------------------------------------------------
__global__ void vq_prep(const float* __restrict__ vec) {
    int i = blockIdx.x * blockDim.x + threadIdx.x;   // 0 .. 65535
    if (i < KDIM) {
        double s = 0.0;
        #pragma unroll 8
        for (int d = 0; d < DDIM; ++d) {
            float v = vec[(size_t)d * KDIM + i];
            s += (double)v * (double)v;
        }
        g_v2[i] = (float)s;
    }
    if (i < 256) g_partials[i] = 0.0;
    g_candcnt[i] = 0;
}

// ---------------------------------------------------------------------------
// Kernel A2: transpose codebook to (K,D) fp32 + bf16
// ---------------------------------------------------------------------------
__global__ void vq_transpose(const float* __restrict__ vec) {
    __shared__ float tile[32][33];
    int k0 = blockIdx.x * 32, d0 = blockIdx.y * 32;
    int tx = threadIdx.x, ty = threadIdx.y;       // (32, 8)
    #pragma unroll
    for (int i = 0; i < 4; ++i)
        tile[ty + 8 * i][tx] = vec[(size_t)(d0 + ty + 8 * i) * KDIM + k0 + tx];
    __syncthreads();
    #pragma unroll
    for (int i = 0; i < 4; ++i) {
        int kl = ty + 8 * i;
        float v = tile[tx][kl];
        size_t o = (size_t)(k0 + kl) * DDIM + d0 + tx;
        g_vT[o]  = v;
        g_vTh[o] = __float2bfloat16_rn(v);
    }
}

// ---------------------------------------------------------------------------
// Kernel B: Phase 1 + fused Phase 2 tail.
//   256 thr = 8 warps (4m x 2n). CTA: 128 rows x full K; N-tiles of 128.
//   Warp tile m32 x n64. x resident in smem (8 chunks of [128][40] bf16),
//   v streamed per chunk into 2 buffers -> ONE sync per chunk.
//   Tail: 8 warps x 16 rows each -> exact rescore + gather + loss.
// ---------------------------------------------------------------------------
#define PM   128
#define PN   128
#define PNT  (KDIM / PN)    // 32
#define PKC  32
#define NCH  (DDIM / PKC)   // 8
#define TOT  (PNT * NCH)    // 256 chunks
#define XSTR 40             // padded bf16 stride; 80B row stride walks banks
#define SM_MMA_BYTES ((NCH * PM * XSTR + 2 * PN * XSTR) * 2)   // 102400

__global__ __launch_bounds__(256, 2) void vq_mma(
        const float* __restrict__ x, float* __restrict__ out,
        float* __restrict__ out_idx, int write_idx) {
    extern __shared__ __nv_bfloat16 smh[];
    __nv_bfloat16* xs = smh;                       // [NCH][PM][XSTR]
    __nv_bfloat16* vs = smh + NCH * PM * XSTR;     // [2][PN][XSTR]

    const int t    = threadIdx.x;
    const int lane = t & 31;
    const int w    = t >> 5;
    const int wm   = w & 3;            // row group: wm*32 .. +31
    const int wn   = w >> 2;           // col group: wn*64 .. +63
    const int g    = lane >> 2;
    const int tig  = lane & 3;
    const int row0 = blockIdx.x * PM;

    const int lr = t >> 1, lh = t & 1;             // loader role: row, half

    // ---- stage resident x tile (8 chunks), fp32 -> bf16 in registers ----
    #pragma unroll
    for (int c = 0; c < NCH; ++c) {
        const float4* src = (const float4*)(x + (size_t)(row0 + lr) * DDIM
                                            + c * PKC + lh * 16);
        float4 f0 = src[0], f1 = src[1], f2 = src[2], f3 = src[3];
        __nv_bfloat16 hb[16];
        hb[0]  = __float2bfloat16_rn(f0.x); hb[1]  = __float2bfloat16_rn(f0.y);
        hb[2]  = __float2bfloat16_rn(f0.z); hb[3]  = __float2bfloat16_rn(f0.w);
        hb[4]  = __float2bfloat16_rn(f1.x); hb[5]  = __float2bfloat16_rn(f1.y);
        hb[6]  = __float2bfloat16_rn(f1.z); hb[7]  = __float2bfloat16_rn(f1.w);
        hb[8]  = __float2bfloat16_rn(f2.x); hb[9]  = __float2bfloat16_rn(f2.y);
        hb[10] = __float2bfloat16_rn(f2.z); hb[11] = __float2bfloat16_rn(f2.w);
        hb[12] = __float2bfloat16_rn(f3.x); hb[13] = __float2bfloat16_rn(f3.y);
        hb[14] = __float2bfloat16_rn(f3.z); hb[15] = __float2bfloat16_rn(f3.w);
        __nv_bfloat16* dst = xs + (c * PM + lr) * XSTR + lh * 16;
        *(uint4*)dst       = *(const uint4*)(hb);
        *(uint4*)(dst + 8) = *(const uint4*)(hb + 8);
    }

    // ---- prologue: chunk 0 -> buf0 directly; chunk 1 -> registers ----
    uint4 pv0, pv1;
    {
        const uint4* s0 = (const uint4*)(g_vTh + (size_t)lr * DDIM + lh * 16);
        __nv_bfloat16* dst = vs + lr * XSTR + lh * 16;
        *(uint4*)dst       = s0[0];
        *(uint4*)(dst + 8) = s0[1];
        const uint4* s1 = (const uint4*)(g_vTh + (size_t)lr * DDIM + PKC + lh * 16);
        pv0 = s1[0]; pv1 = s1[1];
    }
    __syncthreads();

    // ---- ldmatrix lane-dependent base offsets (bytes) — validated mapping ----
    const uint32_t xs_addr = (uint32_t)__cvta_generic_to_shared(xs);
    const uint32_t vs_addr = (uint32_t)__cvta_generic_to_shared(vs);
    const uint32_t a_lane = xs_addr +
        (((wm * 32 + (lane & 7) + ((lane >> 3) & 1) * 8) * XSTR
          + (lane >> 4) * 8) << 1);
    const uint32_t b_lane = vs_addr +
        (((wn * 64 + (lane & 7) + ((lane >> 4) & 1) * 8) * XSTR
          + ((lane >> 3) & 1) * 8) << 1);

    float runmin[4];
    #pragma unroll
    for (int j = 0; j < 4; ++j) runmin[j] = CUDART_INF_F;

    for (int nt = 0; nt < PNT; ++nt) {
        float acc[2][8][4];
        #pragma unroll
        for (int mf = 0; mf < 2; ++mf)
            #pragma unroll
            for (int nf = 0; nf < 8; ++nf)
                #pragma unroll
                for (int e = 0; e < 4; ++e) acc[mf][nf][e] = 0.0f;

        #pragma unroll 1
        for (int c = 0; c < NCH; ++c) {
            const int ch  = nt * NCH + c;
            const int buf = ch & 1;

            // store chunk ch+1 (in regs) into the other buffer — overlapped
            if (ch + 1 < TOT) {
                __nv_bfloat16* dst = vs + (buf ^ 1) * PN * XSTR + lr * XSTR + lh * 16;
                *(uint4*)dst       = pv0;
                *(uint4*)(dst + 8) = pv1;
            }
            // prefetch chunk ch+2 — overlapped with MMAs below
            if (ch + 2 < TOT) {
                int n2 = (ch + 2) >> 3, c2 = (ch + 2) & 7;
                const uint4* s2 = (const uint4*)(g_vTh +
                    (size_t)(n2 * PN + lr) * DDIM + c2 * PKC + lh * 16);
                pv0 = s2[0]; pv1 = s2[1];
            }

            const uint32_t a_ch = a_lane + ((c * PM * XSTR) << 1);
            const uint32_t b_ch = b_lane + ((buf * PN * XSTR) << 1);
            #pragma unroll
            for (int kh = 0; kh < 2; ++kh) {
                const uint32_t koff = (kh * 16) << 1;
                uint32_t a[2][4];
                ldm_x4(a[0], a_ch + koff);
                ldm_x4(a[1], a_ch + ((16 * XSTR) << 1) + koff);
                #pragma unroll
                for (int p = 0; p < 4; ++p) {
                    uint32_t bb[4];
                    ldm_x4(bb, b_ch + ((p * 16 * XSTR) << 1) + koff);
                    #pragma unroll
                    for (int mf = 0; mf < 2; ++mf) {
                        mma_bf16(acc[mf][2 * p],     a[mf], &bb[0]);
                        mma_bf16(acc[mf][2 * p + 1], a[mf], &bb[2]);
                    }
                }
            }
            __syncthreads();   // single barrier per chunk
        }

        // ---- epilogue: running min + candidate collect (validated) ----
        const int kt0 = nt * PN + wn * 64;
        #pragma unroll
        for (int j = 0; j < 4; ++j) {
            const int mf = j >> 1, che = (j & 1) * 2;
            const int R = row0 + wm * 32 + ((j & 1) << 3) + ((j >> 1) << 4) + g;
            float tmin = CUDART_INF_F;
            #pragma unroll
            for (int nf = 0; nf < 8; ++nf) {
                int k = kt0 + nf * 8 + tig * 2;
                float2 c2 = *(const float2*)(g_v2 + k);
                float s0 = fmaf(-2.0f, acc[mf][nf][che + 0], c2.x);
                float s1 = fmaf(-2.0f, acc[mf][nf][che + 1], c2.y);
                tmin = fminf(tmin, fminf(s0, s1));
            }
            tmin = fminf(tmin, __shfl_xor_sync(0xffffffffu, tmin, 1));
            tmin = fminf(tmin, __shfl_xor_sync(0xffffffffu, tmin, 2));
            runmin[j] = fminf(runmin[j], tmin);
            float thr = runmin[j] + TAU;
            #pragma unroll
            for (int nf = 0; nf < 8; ++nf) {
                int k = kt0 + nf * 8 + tig * 2;
                float2 c2 = *(const float2*)(g_v2 + k);
                float s0 = fmaf(-2.0f, acc[mf][nf][che + 0], c2.x);
                float s1 = fmaf(-2.0f, acc[mf][nf][che + 1], c2.y);
                if (s0 <= thr) {
                    int pos = atomicAdd(&g_candcnt[R], 1);
                    if (pos < CAP) g_cand[R * CAP + pos] = k;
                }
                if (s1 <= thr) {
                    int pos = atomicAdd(&g_candcnt[R], 1);
                    if (pos < CAP) g_cand[R * CAP + pos] = k + 1;
                }
            }
        }
    }

    // ======================================================================
    // FUSED TAIL (Phase 2): all candidates for rows row0..row0+127 are now
    // collected by this CTA. Make them visible, then each warp rescores 16
    // rows with the validated exact chain.
    // ======================================================================
    __threadfence_block();
    __syncthreads();

    #pragma unroll 1
    for (int rr = 0; rr < 16; ++rr) {
        int row = row0 + w * 16 + rr;
        const float* xp = x + (size_t)row * DDIM;
        float xr[8];
        #pragma unroll
        for (int i = 0; i < 8; ++i) xr[i] = xp[lane + 32 * i];

        // A_n: bit-exact XLA:GPU warp-reduce order (validated rounds 3-14)
        float Aacc = 0.0f;
        #pragma unroll
        for (int i = 0; i < 8; ++i)
            Aacc = __fadd_rn(Aacc, __fmul_rn(xr[i], xr[i]));
        #pragma unroll
        for (int off = 16; off > 0; off >>= 1)
            Aacc = __fadd_rn(Aacc, __shfl_down_sync(0xffffffffu, Aacc, off));
        float A = __shfl_sync(0xffffffffu, Aacc, 0);

        int cnt = g_candcnt[row];
        float best = CUDART_INF_F;
        int   bidx = 0x7fffffff;

        int iters = (cnt <= CAP) ? cnt : KDIM;
        for (int j = 0; j < iters; ++j) {
            int k = (cnt <= CAP) ? g_cand[row * CAP + j] : j;
            const float* vp = g_vT + (size_t)k * DDIM;
            float d = 0.0f;
            #pragma unroll
            for (int i = 0; i < 8; ++i) d = fmaf(xr[i], vp[lane + 32 * i], d);
            #pragma unroll
            for (int off = 16; off > 0; off >>= 1)
                d = __fadd_rn(d, __shfl_xor_sync(0xffffffffu, d, off));
            float s = __fadd_rn(__fsub_rn(A, __fmul_rn(2.0f, d)), g_v2[k]);
            if (s < best || (s == best && k < bidx)) { best = s; bidx = k; }
        }

        // gather winner + straight-through output + loss partial
        const float* vp = g_vT + (size_t)bidx * DDIM;
        float* op = out + (size_t)row * DDIM;
        double accd = 0.0;
        #pragma unroll
        for (int i = 0; i < 8; ++i) {
            float q  = vp[lane + 32 * i];
            float xv = xr[i];
            op[lane + 32 * i] = __fadd_rn(xv, __fsub_rn(q, xv));
            double dd = (double)xv - (double)q;
            accd += dd * dd;
        }
        #pragma unroll
        for (int off = 16; off > 0; off >>= 1)
            accd += __shfl_down_sync(0xffffffffu, accd, off);
        if (lane == 0) {
            atomicAdd(&g_partials[row & 255], accd);
            if (write_idx) out_idx[row] = (float)bidx;
        }
    }
}

// ---------------------------------------------------------------------------
// Kernel C: finalize losses
// ---------------------------------------------------------------------------
__global__ void vq_final(float* __restrict__ out, long long nd, int has_extra) {
    __shared__ double sd[256];
    sd[threadIdx.x] = g_partials[threadIdx.x];
    __syncthreads();
    #pragma unroll
    for (int s = 128; s > 0; s >>= 1) {
        if (threadIdx.x < s) sd[threadIdx.x] += sd[threadIdx.x + s];
        __syncthreads();
    }
    if (threadIdx.x == 0 && has_extra) {
        float l = (float)(sd[0] / (double)nd);
        out[nd]     = l;
        out[nd + 1] = l;
    }
}

// ---------------------------------------------------------------------------
extern "C" void kernel_launch(void* const* d_in, const int* in_sizes, int n_in,
                              void* d_out, int out_size) {
    const float* x   = (const float*)d_in[0];
    const float* vec = (const float*)d_in[1];
    float* out = (float*)d_out;

    int n = in_sizes[0] / DDIM;                 // 65536 rows
    long long nd = (long long)n * DDIM;
    int has_extra = ((long long)out_size >= nd + 2 + n) ? 1 : 0;

    cudaFuncSetAttribute(vq_mma, cudaFuncAttributeMaxDynamicSharedMemorySize,
                         SM_MMA_BYTES);

    vq_prep<<<MAXN / 256, 256>>>(vec);
    vq_transpose<<<dim3(KDIM / 32, DDIM / 32), dim3(32, 8)>>>(vec);
    vq_mma<<<n / PM, 256, SM_MMA_BYTES>>>(x, out, out + nd + 2, has_extra);
    vq_final<<<1, 256>>>(out, nd, has_extra);
}

// round 16
// speedup vs baseline: 1.0920x; 1.0920x over previous
#include <cuda_runtime.h>
#include <cuda_bf16.h>
#include <math_constants.h>
#include <cstdint>

// ===========================================================================
// VectorQuantizer: x (64,1024,256) f32, codebook vectors (256,4096) f32.
// Outputs (flattened f32): [0,N*D) quantized_st; [N*D] dict_loss; [N*D+1]
// commitment_loss; [N*D+2, +N) indices as float.
//
// Phase 1: bf16 HMMA (mma.sync m16n8k16 + ldmatrix, family-wide PTX) approx
//          scores; per-row running min + candidate collect (<= runmin + TAU).
//          Round-14 champion kernel, byte-identical.
// Phase 2: exact fp32 rescore with the reference rounding chain
//          s = fl(fl(A - 2*dot) + C); A inline, bit-exact XLA warp-reduce
//          order. NEW: float4 candidate loads + ILP-2 over candidate pairs.
// ===========================================================================

#define DDIM 256
#define KDIM 4096
#define MAXN 65536
#define CAP  32
#define TAU  2.5e-3f

__device__ float         g_v2[KDIM];
__device__ double        g_partials[256];
__device__ float         g_vT[KDIM * DDIM];
__device__ __nv_bfloat16 g_vTh[KDIM * DDIM];
__device__ int           g_candcnt[MAXN];
__device__ int           g_cand[MAXN * CAP];

// ---------------------------------------------------------------------------
__device__ __forceinline__ void mma_bf16(float* d, const uint32_t* a,
                                         const uint32_t* b) {
    asm volatile(
        "mma.sync.aligned.m16n8k16.row.col.f32.bf16.bf16.f32 "
        "{%0,%1,%2,%3}, {%4,%5,%6,%7}, {%8,%9}, {%0,%1,%2,%3};"
        : "+f"(d[0]), "+f"(d[1]), "+f"(d[2]), "+f"(d[3])
        : "r"(a[0]), "r"(a[1]), "r"(a[2]), "r"(a[3]), "r"(b[0]), "r"(b[1]));
}
__device__ __forceinline__ void ldm_x4(uint32_t* r, uint32_t addr) {
    asm volatile("ldmatrix.sync.aligned.m8n8.x4.shared.b16 {%0,%1,%2,%3}, [%4];"
        : "=r"(r[0]), "=r"(r[1]), "=r"(r[2]), "=r"(r[3]) : "r"(addr));
}
__device__ __forceinline__ float dot8(float4 x0, float4 x1, float4 a, float4 b) {
    float d = 0.0f;
    d = fmaf(x0.x, a.x, d); d = fmaf(x0.y, a.y, d);
    d = fmaf(x0.z, a.z, d); d = fmaf(x0.w, a.w, d);
    d = fmaf(x1.x, b.x, d); d = fmaf(x1.y, b.y, d);
    d = fmaf(x1.z, b.z, d); d = fmaf(x1.w, b.w, d);
    return d;
}

// ---------------------------------------------------------------------------
// Kernel A1: C_k = ||v_k||^2 (fp64); zero loss partials + cand counts
// ---------------------------------------------------------------------------
__global__ void vq_prep(const float* __restrict__ vec) {
    int i = blockIdx.x * blockDim.x + threadIdx.x;   // 0 .. 65535
    if (i < KDIM) {
        double s = 0.0;
        #pragma unroll 8
        for (int d = 0; d < DDIM; ++d) {
            float v = vec[(size_t)d * KDIM + i];
            s += (double)v * (double)v;
        }
        g_v2[i] = (float)s;
    }
    if (i < 256) g_partials[i] = 0.0;
    g_candcnt[i] = 0;
}

// ---------------------------------------------------------------------------
// Kernel A2: transpose codebook to (K,D) fp32 + bf16
// ---------------------------------------------------------------------------
__global__ void vq_transpose(const float* __restrict__ vec) {
    __shared__ float tile[32][33];
    int k0 = blockIdx.x * 32, d0 = blockIdx.y * 32;
    int tx = threadIdx.x, ty = threadIdx.y;       // (32, 8)
    #pragma unroll
    for (int i = 0; i < 4; ++i)
        tile[ty + 8 * i][tx] = vec[(size_t)(d0 + ty + 8 * i) * KDIM + k0 + tx];
    __syncthreads();
    #pragma unroll
    for (int i = 0; i < 4; ++i) {
        int kl = ty + 8 * i;
        float v = tile[tx][kl];
        size_t o = (size_t)(k0 + kl) * DDIM + d0 + tx;
        g_vT[o]  = v;
        g_vTh[o] = __float2bfloat16_rn(v);
    }
}

// ---------------------------------------------------------------------------
// Kernel B: Phase 1 — bf16 HMMA prefilter (round-14 champion, unchanged).
// ---------------------------------------------------------------------------
#define PM   128
#define PN   128
#define PNT  (KDIM / PN)    // 32
#define PKC  32
#define NCH  (DDIM / PKC)   // 8
#define TOT  (PNT * NCH)    // 256 chunks
#define XSTR 40             // padded bf16 stride; 80B row stride walks banks
#define SM_MMA_BYTES ((NCH * PM * XSTR + 2 * PN * XSTR) * 2)   // 102400

__global__ __launch_bounds__(256, 2) void vq_mma(const float* __restrict__ x) {
    extern __shared__ __nv_bfloat16 smh[];
    __nv_bfloat16* xs = smh;                       // [NCH][PM][XSTR]
    __nv_bfloat16* vs = smh + NCH * PM * XSTR;     // [2][PN][XSTR]

    const int t    = threadIdx.x;
    const int lane = t & 31;
    const int w    = t >> 5;
    const int wm   = w & 3;            // row group: wm*32 .. +31
    const int wn   = w >> 2;           // col group: wn*64 .. +63
    const int g    = lane >> 2;
    const int tig  = lane & 3;
    const int row0 = blockIdx.x * PM;

    const int lr = t >> 1, lh = t & 1;             // loader role: row, half

    // ---- stage resident x tile (8 chunks), fp32 -> bf16 in registers ----
    #pragma unroll
    for (int c = 0; c < NCH; ++c) {
        const float4* src = (const float4*)(x + (size_t)(row0 + lr) * DDIM
                                            + c * PKC + lh * 16);
        float4 f0 = src[0], f1 = src[1], f2 = src[2], f3 = src[3];
        __nv_bfloat16 hb[16];
        hb[0]  = __float2bfloat16_rn(f0.x); hb[1]  = __float2bfloat16_rn(f0.y);
        hb[2]  = __float2bfloat16_rn(f0.z); hb[3]  = __float2bfloat16_rn(f0.w);
        hb[4]  = __float2bfloat16_rn(f1.x); hb[5]  = __float2bfloat16_rn(f1.y);
        hb[6]  = __float2bfloat16_rn(f1.z); hb[7]  = __float2bfloat16_rn(f1.w);
        hb[8]  = __float2bfloat16_rn(f2.x); hb[9]  = __float2bfloat16_rn(f2.y);
        hb[10] = __float2bfloat16_rn(f2.z); hb[11] = __float2bfloat16_rn(f2.w);
        hb[12] = __float2bfloat16_rn(f3.x); hb[13] = __float2bfloat16_rn(f3.y);
        hb[14] = __float2bfloat16_rn(f3.z); hb[15] = __float2bfloat16_rn(f3.w);
        __nv_bfloat16* dst = xs + (c * PM + lr) * XSTR + lh * 16;
        *(uint4*)dst       = *(const uint4*)(hb);
        *(uint4*)(dst + 8) = *(const uint4*)(hb + 8);
    }

    // ---- prologue: chunk 0 -> buf0 directly; chunk 1 -> registers ----
    uint4 pv0, pv1;
    {
        const uint4* s0 = (const uint4*)(g_vTh + (size_t)lr * DDIM + lh * 16);
        __nv_bfloat16* dst = vs + lr * XSTR + lh * 16;
        *(uint4*)dst       = s0[0];
        *(uint4*)(dst + 8) = s0[1];
        const uint4* s1 = (const uint4*)(g_vTh + (size_t)lr * DDIM + PKC + lh * 16);
        pv0 = s1[0]; pv1 = s1[1];
    }
    __syncthreads();

    // ---- ldmatrix lane-dependent base offsets (bytes) — validated mapping ----
    const uint32_t xs_addr = (uint32_t)__cvta_generic_to_shared(xs);
    const uint32_t vs_addr = (uint32_t)__cvta_generic_to_shared(vs);
    const uint32_t a_lane = xs_addr +
        (((wm * 32 + (lane & 7) + ((lane >> 3) & 1) * 8) * XSTR
          + (lane >> 4) * 8) << 1);
    const uint32_t b_lane = vs_addr +
        (((wn * 64 + (lane & 7) + ((lane >> 4) & 1) * 8) * XSTR
          + ((lane >> 3) & 1) * 8) << 1);

    float runmin[4];
    #pragma unroll
    for (int j = 0; j < 4; ++j) runmin[j] = CUDART_INF_F;

    for (int nt = 0; nt < PNT; ++nt) {
        float acc[2][8][4];
        #pragma unroll
        for (int mf = 0; mf < 2; ++mf)
            #pragma unroll
            for (int nf = 0; nf < 8; ++nf)
                #pragma unroll
                for (int e = 0; e < 4; ++e) acc[mf][nf][e] = 0.0f;

        #pragma unroll 1
        for (int c = 0; c < NCH; ++c) {
            const int ch  = nt * NCH + c;
            const int buf = ch & 1;

            // store chunk ch+1 (in regs) into the other buffer — overlapped
            if (ch + 1 < TOT) {
                __nv_bfloat16* dst = vs + (buf ^ 1) * PN * XSTR + lr * XSTR + lh * 16;
                *(uint4*)dst       = pv0;
                *(uint4*)(dst + 8) = pv1;
            }
            // prefetch chunk ch+2 — overlapped with MMAs below
            if (ch + 2 < TOT) {
                int n2 = (ch + 2) >> 3, c2 = (ch + 2) & 7;
                const uint4* s2 = (const uint4*)(g_vTh +
                    (size_t)(n2 * PN + lr) * DDIM + c2 * PKC + lh * 16);
                pv0 = s2[0]; pv1 = s2[1];
            }

            const uint32_t a_ch = a_lane + ((c * PM * XSTR) << 1);
            const uint32_t b_ch = b_lane + ((buf * PN * XSTR) << 1);
            #pragma unroll
            for (int kh = 0; kh < 2; ++kh) {
                const uint32_t koff = (kh * 16) << 1;
                uint32_t a[2][4];
                ldm_x4(a[0], a_ch + koff);
                ldm_x4(a[1], a_ch + ((16 * XSTR) << 1) + koff);
                #pragma unroll
                for (int p = 0; p < 4; ++p) {
                    uint32_t bb[4];
                    ldm_x4(bb, b_ch + ((p * 16 * XSTR) << 1) + koff);
                    #pragma unroll
                    for (int mf = 0; mf < 2; ++mf) {
                        mma_bf16(acc[mf][2 * p],     a[mf], &bb[0]);
                        mma_bf16(acc[mf][2 * p + 1], a[mf], &bb[2]);
                    }
                }
            }
            __syncthreads();   // single barrier per chunk
        }

        // ---- epilogue: running min + candidate collect (validated) ----
        const int kt0 = nt * PN + wn * 64;
        #pragma unroll
        for (int j = 0; j < 4; ++j) {
            const int mf = j >> 1, che = (j & 1) * 2;
            const int R = row0 + wm * 32 + ((j & 1) << 3) + ((j >> 1) << 4) + g;
            float tmin = CUDART_INF_F;
            #pragma unroll
            for (int nf = 0; nf < 8; ++nf) {
                int k = kt0 + nf * 8 + tig * 2;
                float2 c2 = *(const float2*)(g_v2 + k);
                float s0 = fmaf(-2.0f, acc[mf][nf][che + 0], c2.x);
                float s1 = fmaf(-2.0f, acc[mf][nf][che + 1], c2.y);
                tmin = fminf(tmin, fminf(s0, s1));
            }
            tmin = fminf(tmin, __shfl_xor_sync(0xffffffffu, tmin, 1));
            tmin = fminf(tmin, __shfl_xor_sync(0xffffffffu, tmin, 2));
            runmin[j] = fminf(runmin[j], tmin);
            float thr = runmin[j] + TAU;
            #pragma unroll
            for (int nf = 0; nf < 8; ++nf) {
                int k = kt0 + nf * 8 + tig * 2;
                float2 c2 = *(const float2*)(g_v2 + k);
                float s0 = fmaf(-2.0f, acc[mf][nf][che + 0], c2.x);
                float s1 = fmaf(-2.0f, acc[mf][nf][che + 1], c2.y);
                if (s0 <= thr) {
                    int pos = atomicAdd(&g_candcnt[R], 1);
                    if (pos < CAP) g_cand[R * CAP + pos] = k;
                }
                if (s1 <= thr) {
                    int pos = atomicAdd(&g_candcnt[R], 1);
                    if (pos < CAP) g_cand[R * CAP + pos] = k + 1;
                }
            }
        }
    }
}

// ---------------------------------------------------------------------------
// Kernel C: Phase 2 — inline XLA-order A + exact rescore (float4 loads,
//   ILP-2 candidate pairs) + gather + ST output + loss. Warp per row.
// ---------------------------------------------------------------------------
__global__ __launch_bounds__(256) void vq_finish(
        const float* __restrict__ x, float* __restrict__ out,
        float* __restrict__ out_idx, int write_idx) {
    int warp = threadIdx.x >> 5;
    int lane = threadIdx.x & 31;
    int row  = blockIdx.x * 8 + warp;

    const float* xp = x + (size_t)row * DDIM;

    // A_n: bit-exact XLA:GPU warp-reduce order (validated rounds 3-14):
    // scalar strided layout, sequential mul/add per lane, shfl_down 16..1.
    float Aacc = 0.0f;
    #pragma unroll
    for (int i = 0; i < 8; ++i) {
        float v = xp[lane + 32 * i];
        Aacc = __fadd_rn(Aacc, __fmul_rn(v, v));
    }
    #pragma unroll
    for (int off = 16; off > 0; off >>= 1)
        Aacc = __fadd_rn(Aacc, __shfl_down_sync(0xffffffffu, Aacc, off));
    float A = __shfl_sync(0xffffffffu, Aacc, 0);

    // float4 lane-layout copy of the row for dots / gather (order-insensitive)
    const float4* xp4 = (const float4*)xp;
    float4 xq0 = xp4[lane], xq1 = xp4[lane + 32];

    int cnt = g_candcnt[row];
    float best = CUDART_INF_F;
    int   bidx = 0x7fffffff;

    const bool ok = (cnt <= CAP);
    int iters = ok ? cnt : KDIM;
    const int* cl = g_cand + row * CAP;

    int j = 0;
    for (; j + 2 <= iters; j += 2) {
        int k0 = ok ? cl[j]     : j;
        int k1 = ok ? cl[j + 1] : j + 1;
        const float4* v0 = (const float4*)(g_vT + (size_t)k0 * DDIM);
        const float4* v1 = (const float4*)(g_vT + (size_t)k1 * DDIM);
        float4 a0 = v0[lane], b0 = v0[lane + 32];
        float4 a1 = v1[lane], b1 = v1[lane + 32];
        float d0 = dot8(xq0, xq1, a0, b0);
        float d1 = dot8(xq0, xq1, a1, b1);
        #pragma unroll
        for (int off = 16; off > 0; off >>= 1) {
            d0 = __fadd_rn(d0, __shfl_xor_sync(0xffffffffu, d0, off));
            d1 = __fadd_rn(d1, __shfl_xor_sync(0xffffffffu, d1, off));
        }
        float s0 = __fadd_rn(__fsub_rn(A, __fmul_rn(2.0f, d0)), g_v2[k0]);
        float s1 = __fadd_rn(__fsub_rn(A, __fmul_rn(2.0f, d1)), g_v2[k1]);
        if (s0 < best || (s0 == best && k0 < bidx)) { best = s0; bidx = k0; }
        if (s1 < best || (s1 == best && k1 < bidx)) { best = s1; bidx = k1; }
    }
    for (; j < iters; ++j) {
        int k = ok ? cl[j] : j;
        const float4* v0 = (const float4*)(g_vT + (size_t)k * DDIM);
        float4 a0 = v0[lane], b0 = v0[lane + 32];
        float d = dot8(xq0, xq1, a0, b0);
        #pragma unroll
        for (int off = 16; off > 0; off >>= 1)
            d = __fadd_rn(d, __shfl_xor_sync(0xffffffffu, d, off));
        float s = __fadd_rn(__fsub_rn(A, __fmul_rn(2.0f, d)), g_v2[k]);
        if (s < best || (s == best && k < bidx)) { best = s; bidx = k; }
    }

    // gather winner + straight-through output + loss partial (float4 layout,
    // position-matched -> identical output values)
    const float4* vp4 = (const float4*)(g_vT + (size_t)bidx * DDIM);
    float4* op4 = (float4*)(out + (size_t)row * DDIM);
    double accd = 0.0;
    #pragma unroll
    for (int i = 0; i < 2; ++i) {
        float4 q = vp4[lane + 32 * i];
        float4 v = (i == 0) ? xq0 : xq1;
        float4 o;
        o.x = __fadd_rn(v.x, __fsub_rn(q.x, v.x));
        o.y = __fadd_rn(v.y, __fsub_rn(q.y, v.y));
        o.z = __fadd_rn(v.z, __fsub_rn(q.z, v.z));
        o.w = __fadd_rn(v.w, __fsub_rn(q.w, v.w));
        op4[lane + 32 * i] = o;
        double dx = (double)v.x - (double)q.x, dy = (double)v.y - (double)q.y;
        double dz = (double)v.z - (double)q.z, dw = (double)v.w - (double)q.w;
        accd += dx * dx + dy * dy + dz * dz + dw * dw;
    }
    #pragma unroll
    for (int off = 16; off > 0; off >>= 1)
        accd += __shfl_down_sync(0xffffffffu, accd, off);
    if (lane == 0) {
        atomicAdd(&g_partials[row & 255], accd);
        if (write_idx) out_idx[row] = (float)bidx;
    }
}

// ---------------------------------------------------------------------------
// Kernel D: finalize losses
// ---------------------------------------------------------------------------
__global__ void vq_final(float* __restrict__ out, long long nd, int has_extra) {
    __shared__ double sd[256];
    sd[threadIdx.x] = g_partials[threadIdx.x];
    __syncthreads();
    #pragma unroll
    for (int s = 128; s > 0; s >>= 1) {
        if (threadIdx.x < s) sd[threadIdx.x] += sd[threadIdx.x + s];
        __syncthreads();
    }
    if (threadIdx.x == 0 && has_extra) {
        float l = (float)(sd[0] / (double)nd);
        out[nd]     = l;
        out[nd + 1] = l;
    }
}

// ---------------------------------------------------------------------------
extern "C" void kernel_launch(void* const* d_in, const int* in_sizes, int n_in,
                              void* d_out, int out_size) {
    const float* x   = (const float*)d_in[0];
    const float* vec = (const float*)d_in[1];
    float* out = (float*)d_out;

    int n = in_sizes[0] / DDIM;                 // 65536 rows
    long long nd = (long long)n * DDIM;
    int has_extra = ((long long)out_size >= nd + 2 + n) ? 1 : 0;

    cudaFuncSetAttribute(vq_mma, cudaFuncAttributeMaxDynamicSharedMemorySize,
                         SM_MMA_BYTES);

    vq_prep<<<MAXN / 256, 256>>>(vec);
    vq_transpose<<<dim3(KDIM / 32, DDIM / 32), dim3(32, 8)>>>(vec);
    vq_mma<<<n / PM, 256, SM_MMA_BYTES>>>(x);
    vq_finish<<<n / 8, 256>>>(x, out, out + nd + 2, has_extra);
    vq_final<<<1, 256>>>(out, nd, has_extra);
}

// round 17
// speedup vs baseline: 1.1165x; 1.0224x over previous
#include <cuda_runtime.h>
#include <cuda_bf16.h>
#include <math_constants.h>
#include <cstdint>

// ===========================================================================
// VectorQuantizer: x (64,1024,256) f32, codebook vectors (256,4096) f32.
// Outputs (flattened f32): [0,N*D) quantized_st; [N*D] dict_loss; [N*D+1]
// commitment_loss; [N*D+2, +N) indices as float.
//
// Phase 1: bf16 HMMA (mma.sync m16n8k16 + ldmatrix) approx scores; per-row
//          running min + candidate collect (<= runmin + TAU). NEW: store each
//          candidate's approx score and publish the per-row global approx min
//          (atomicMin, order-preserving uint encoding).
// Phase 2: exact fp32 rescore ONLY of candidates with s~ <= amin + TAU
//          (superset of the argmin by the same 8-sigma noise bound);
//          reference rounding chain s = fl(fl(A - 2*dot) + C), A inline
//          bit-exact XLA warp-reduce order; gather + ST output + loss.
// ===========================================================================

#define DDIM 256
#define KDIM 4096
#define MAXN 65536
#define CAP  32
#define TAU  2.5e-3f

__device__ float         g_v2[KDIM];
__device__ double        g_partials[256];
__device__ float         g_vT[KDIM * DDIM];
__device__ __nv_bfloat16 g_vTh[KDIM * DDIM];
__device__ int           g_candcnt[MAXN];
__device__ int           g_cand[MAXN * CAP];
__device__ float         g_cscore[MAXN * CAP];
__device__ unsigned      g_amin[MAXN];

// ---------------------------------------------------------------------------
__device__ __forceinline__ void mma_bf16(float* d, const uint32_t* a,
                                         const uint32_t* b) {
    asm volatile(
        "mma.sync.aligned.m16n8k16.row.col.f32.bf16.bf16.f32 "
        "{%0,%1,%2,%3}, {%4,%5,%6,%7}, {%8,%9}, {%0,%1,%2,%3};"
        : "+f"(d[0]), "+f"(d[1]), "+f"(d[2]), "+f"(d[3])
        : "r"(a[0]), "r"(a[1]), "r"(a[2]), "r"(a[3]), "r"(b[0]), "r"(b[1]));
}
__device__ __forceinline__ void ldm_x4(uint32_t* r, uint32_t addr) {
    asm volatile("ldmatrix.sync.aligned.m8n8.x4.shared.b16 {%0,%1,%2,%3}, [%4];"
        : "=r"(r[0]), "=r"(r[1]), "=r"(r[2]), "=r"(r[3]) : "r"(addr));
}
// order-preserving float<->uint encoding (for atomicMin over signed floats)
__device__ __forceinline__ unsigned fenc(float f) {
    int i = __float_as_int(f);
    return (i >= 0) ? ((unsigned)i | 0x80000000u) : ~(unsigned)i;
}
__device__ __forceinline__ float fdec(unsigned u) {
    int i = (u & 0x80000000u) ? (int)(u & 0x7FFFFFFFu) : ~(int)u;
    return __int_as_float(i);
}
__device__ __forceinline__ float dot8(float4 x0, float4 x1, float4 a, float4 b) {
    float d = 0.0f;
    d = fmaf(x0.x, a.x, d); d = fmaf(x0.y, a.y, d);
    d = fmaf(x0.z, a.z, d); d = fmaf(x0.w, a.w, d);
    d = fmaf(x1.x, b.x, d); d = fmaf(x1.y, b.y, d);
    d = fmaf(x1.z, b.z, d); d = fmaf(x1.w, b.w, d);
    return d;
}

// ---------------------------------------------------------------------------
// Kernel A1: C_k = ||v_k||^2 (fp64); zero partials, counts, amin
// ---------------------------------------------------------------------------
__global__ void vq_prep(const float* __restrict__ vec) {
    int i = blockIdx.x * blockDim.x + threadIdx.x;   // 0 .. 65535
    if (i < KDIM) {
        double s = 0.0;
        #pragma unroll 8
        for (int d = 0; d < DDIM; ++d) {
            float v = vec[(size_t)d * KDIM + i];
            s += (double)v * (double)v;
        }
        g_v2[i] = (float)s;
    }
    if (i < 256) g_partials[i] = 0.0;
    g_candcnt[i] = 0;
    g_amin[i] = 0xFFFFFFFFu;
}

// ---------------------------------------------------------------------------
// Kernel A2: transpose codebook to (K,D) fp32 + bf16
// ---------------------------------------------------------------------------
__global__ void vq_transpose(const float* __restrict__ vec) {
    __shared__ float tile[32][33];
    int k0 = blockIdx.x * 32, d0 = blockIdx.y * 32;
    int tx = threadIdx.x, ty = threadIdx.y;       // (32, 8)
    #pragma unroll
    for (int i = 0; i < 4; ++i)
        tile[ty + 8 * i][tx] = vec[(size_t)(d0 + ty + 8 * i) * KDIM + k0 + tx];
    __syncthreads();
    #pragma unroll
    for (int i = 0; i < 4; ++i) {
        int kl = ty + 8 * i;
        float v = tile[tx][kl];
        size_t o = (size_t)(k0 + kl) * DDIM + d0 + tx;
        g_vT[o]  = v;
        g_vTh[o] = __float2bfloat16_rn(v);
    }
}

// ---------------------------------------------------------------------------
// Kernel B: Phase 1 — bf16 HMMA prefilter (champion inner loop, unchanged;
//   epilogue additionally records scores + final per-row approx min).
// ---------------------------------------------------------------------------
#define PM   128
#define PN   128
#define PNT  (KDIM / PN)    // 32
#define PKC  32
#define NCH  (DDIM / PKC)   // 8
#define TOT  (PNT * NCH)    // 256 chunks
#define XSTR 40             // padded bf16 stride; 80B row stride walks banks
#define SM_MMA_BYTES ((NCH * PM * XSTR + 2 * PN * XSTR) * 2)   // 102400

__global__ __launch_bounds__(256, 2) void vq_mma(const float* __restrict__ x) {
    extern __shared__ __nv_bfloat16 smh[];
    __nv_bfloat16* xs = smh;                       // [NCH][PM][XSTR]
    __nv_bfloat16* vs = smh + NCH * PM * XSTR;     // [2][PN][XSTR]

    const int t    = threadIdx.x;
    const int lane = t & 31;
    const int w    = t >> 5;
    const int wm   = w & 3;            // row group: wm*32 .. +31
    const int wn   = w >> 2;           // col group: wn*64 .. +63
    const int g    = lane >> 2;
    const int tig  = lane & 3;
    const int row0 = blockIdx.x * PM;

    const int lr = t >> 1, lh = t & 1;             // loader role: row, half

    // ---- stage resident x tile (8 chunks), fp32 -> bf16 in registers ----
    #pragma unroll
    for (int c = 0; c < NCH; ++c) {
        const float4* src = (const float4*)(x + (size_t)(row0 + lr) * DDIM
                                            + c * PKC + lh * 16);
        float4 f0 = src[0], f1 = src[1], f2 = src[2], f3 = src[3];
        __nv_bfloat16 hb[16];
        hb[0]  = __float2bfloat16_rn(f0.x); hb[1]  = __float2bfloat16_rn(f0.y);
        hb[2]  = __float2bfloat16_rn(f0.z); hb[3]  = __float2bfloat16_rn(f0.w);
        hb[4]  = __float2bfloat16_rn(f1.x); hb[5]  = __float2bfloat16_rn(f1.y);
        hb[6]  = __float2bfloat16_rn(f1.z); hb[7]  = __float2bfloat16_rn(f1.w);
        hb[8]  = __float2bfloat16_rn(f2.x); hb[9]  = __float2bfloat16_rn(f2.y);
        hb[10] = __float2bfloat16_rn(f2.z); hb[11] = __float2bfloat16_rn(f2.w);
        hb[12] = __float2bfloat16_rn(f3.x); hb[13] = __float2bfloat16_rn(f3.y);
        hb[14] = __float2bfloat16_rn(f3.z); hb[15] = __float2bfloat16_rn(f3.w);
        __nv_bfloat16* dst = xs + (c * PM + lr) * XSTR + lh * 16;
        *(uint4*)dst       = *(const uint4*)(hb);
        *(uint4*)(dst + 8) = *(const uint4*)(hb + 8);
    }

    // ---- prologue: chunk 0 -> buf0 directly; chunk 1 -> registers ----
    uint4 pv0, pv1;
    {
        const uint4* s0 = (const uint4*)(g_vTh + (size_t)lr * DDIM + lh * 16);
        __nv_bfloat16* dst = vs + lr * XSTR + lh * 16;
        *(uint4*)dst       = s0[0];
        *(uint4*)(dst + 8) = s0[1];
        const uint4* s1 = (const uint4*)(g_vTh + (size_t)lr * DDIM + PKC + lh * 16);
        pv0 = s1[0]; pv1 = s1[1];
    }
    __syncthreads();

    // ---- ldmatrix lane-dependent base offsets (bytes) — validated mapping ----
    const uint32_t xs_addr = (uint32_t)__cvta_generic_to_shared(xs);
    const uint32_t vs_addr = (uint32_t)__cvta_generic_to_shared(vs);
    const uint32_t a_lane = xs_addr +
        (((wm * 32 + (lane & 7) + ((lane >> 3) & 1) * 8) * XSTR
          + (lane >> 4) * 8) << 1);
    const uint32_t b_lane = vs_addr +
        (((wn * 64 + (lane & 7) + ((lane >> 4) & 1) * 8) * XSTR
          + ((lane >> 3) & 1) * 8) << 1);

    float runmin[4];
    #pragma unroll
    for (int j = 0; j < 4; ++j) runmin[j] = CUDART_INF_F;

    for (int nt = 0; nt < PNT; ++nt) {
        float acc[2][8][4];
        #pragma unroll
        for (int mf = 0; mf < 2; ++mf)
            #pragma unroll
            for (int nf = 0; nf < 8; ++nf)
                #pragma unroll
                for (int e = 0; e < 4; ++e) acc[mf][nf][e] = 0.0f;

        #pragma unroll 1
        for (int c = 0; c < NCH; ++c) {
            const int ch  = nt * NCH + c;
            const int buf = ch & 1;

            // store chunk ch+1 (in regs) into the other buffer — overlapped
            if (ch + 1 < TOT) {
                __nv_bfloat16* dst = vs + (buf ^ 1) * PN * XSTR + lr * XSTR + lh * 16;
                *(uint4*)dst       = pv0;
                *(uint4*)(dst + 8) = pv1;
            }
            // prefetch chunk ch+2 — overlapped with MMAs below
            if (ch + 2 < TOT) {
                int n2 = (ch + 2) >> 3, c2 = (ch + 2) & 7;
                const uint4* s2 = (const uint4*)(g_vTh +
                    (size_t)(n2 * PN + lr) * DDIM + c2 * PKC + lh * 16);
                pv0 = s2[0]; pv1 = s2[1];
            }

            const uint32_t a_ch = a_lane + ((c * PM * XSTR) << 1);
            const uint32_t b_ch = b_lane + ((buf * PN * XSTR) << 1);
            #pragma unroll
            for (int kh = 0; kh < 2; ++kh) {
                const uint32_t koff = (kh * 16) << 1;
                uint32_t a[2][4];
                ldm_x4(a[0], a_ch + koff);
                ldm_x4(a[1], a_ch + ((16 * XSTR) << 1) + koff);
                #pragma unroll
                for (int p = 0; p < 4; ++p) {
                    uint32_t bb[4];
                    ldm_x4(bb, b_ch + ((p * 16 * XSTR) << 1) + koff);
                    #pragma unroll
                    for (int mf = 0; mf < 2; ++mf) {
                        mma_bf16(acc[mf][2 * p],     a[mf], &bb[0]);
                        mma_bf16(acc[mf][2 * p + 1], a[mf], &bb[2]);
                    }
                }
            }
            __syncthreads();   // single barrier per chunk
        }

        // ---- epilogue: running min + candidate collect (+ score record) ----
        const int kt0 = nt * PN + wn * 64;
        #pragma unroll
        for (int j = 0; j < 4; ++j) {
            const int mf = j >> 1, che = (j & 1) * 2;
            const int R = row0 + wm * 32 + ((j & 1) << 3) + ((j >> 1) << 4) + g;
            float tmin = CUDART_INF_F;
            #pragma unroll
            for (int nf = 0; nf < 8; ++nf) {
                int k = kt0 + nf * 8 + tig * 2;
                float2 c2 = *(const float2*)(g_v2 + k);
                float s0 = fmaf(-2.0f, acc[mf][nf][che + 0], c2.x);
                float s1 = fmaf(-2.0f, acc[mf][nf][che + 1], c2.y);
                tmin = fminf(tmin, fminf(s0, s1));
            }
            tmin = fminf(tmin, __shfl_xor_sync(0xffffffffu, tmin, 1));
            tmin = fminf(tmin, __shfl_xor_sync(0xffffffffu, tmin, 2));
            runmin[j] = fminf(runmin[j], tmin);
            float thr = runmin[j] + TAU;
            #pragma unroll
            for (int nf = 0; nf < 8; ++nf) {
                int k = kt0 + nf * 8 + tig * 2;
                float2 c2 = *(const float2*)(g_v2 + k);
                float s0 = fmaf(-2.0f, acc[mf][nf][che + 0], c2.x);
                float s1 = fmaf(-2.0f, acc[mf][nf][che + 1], c2.y);
                if (s0 <= thr) {
                    int pos = atomicAdd(&g_candcnt[R], 1);
                    if (pos < CAP) {
                        g_cand[R * CAP + pos]   = k;
                        g_cscore[R * CAP + pos] = s0;
                    }
                }
                if (s1 <= thr) {
                    int pos = atomicAdd(&g_candcnt[R], 1);
                    if (pos < CAP) {
                        g_cand[R * CAP + pos]   = k + 1;
                        g_cscore[R * CAP + pos] = s1;
                    }
                }
            }
        }
    }

    // publish final per-row approx min (runmin == global min of s~ for row;
    // the two wn-warps both publish -> atomicMin)
    if (tig == 0) {
        #pragma unroll
        for (int j = 0; j < 4; ++j) {
            const int R = row0 + wm * 32 + ((j & 1) << 3) + ((j >> 1) << 4) + g;
            atomicMin(&g_amin[R], fenc(runmin[j]));
        }
    }
}

// ---------------------------------------------------------------------------
// Kernel C: Phase 2 — inline XLA-order A + score-filtered exact rescore +
//   gather + ST output + loss. Warp per row.
// ---------------------------------------------------------------------------
__global__ __launch_bounds__(256) void vq_finish(
        const float* __restrict__ x, float* __restrict__ out,
        float* __restrict__ out_idx, int write_idx) {
    int warp = threadIdx.x >> 5;
    int lane = threadIdx.x & 31;
    int row  = blockIdx.x * 8 + warp;

    const float* xp = x + (size_t)row * DDIM;

    // A_n: bit-exact XLA:GPU warp-reduce order (validated rounds 3-16)
    float Aacc = 0.0f;
    #pragma unroll
    for (int i = 0; i < 8; ++i) {
        float v = xp[lane + 32 * i];
        Aacc = __fadd_rn(Aacc, __fmul_rn(v, v));
    }
    #pragma unroll
    for (int off = 16; off > 0; off >>= 1)
        Aacc = __fadd_rn(Aacc, __shfl_down_sync(0xffffffffu, Aacc, off));
    float A = __shfl_sync(0xffffffffu, Aacc, 0);

    const float4* xp4 = (const float4*)xp;
    float4 xq0 = xp4[lane], xq1 = xp4[lane + 32];

    int cnt = g_candcnt[row];
    float best = CUDART_INF_F;
    int   bidx = 0x7fffffff;

    const bool ok = (cnt <= CAP);
    const float fthr = fdec(g_amin[row]) + TAU;   // final-min threshold
    int iters = ok ? cnt : KDIM;
    const int*   cl = g_cand   + row * CAP;
    const float* cs = g_cscore + row * CAP;

    for (int j = 0; j < iters; ++j) {
        int k;
        if (ok) {
            if (cs[j] > fthr) continue;           // overcollected -> skip
            k = cl[j];
        } else {
            k = j;
        }
        const float4* v0 = (const float4*)(g_vT + (size_t)k * DDIM);
        float4 a0 = v0[lane], b0 = v0[lane + 32];
        float d = dot8(xq0, xq1, a0, b0);
        #pragma unroll
        for (int off = 16; off > 0; off >>= 1)
            d = __fadd_rn(d, __shfl_xor_sync(0xffffffffu, d, off));
        float s = __fadd_rn(__fsub_rn(A, __fmul_rn(2.0f, d)), g_v2[k]);
        if (s < best || (s == best && k < bidx)) { best = s; bidx = k; }
    }

    // gather winner + straight-through output + loss partial
    const float4* vp4 = (const float4*)(g_vT + (size_t)bidx * DDIM);
    float4* op4 = (float4*)(out + (size_t)row * DDIM);
    double accd = 0.0;
    #pragma unroll
    for (int i = 0; i < 2; ++i) {
        float4 q = vp4[lane + 32 * i];
        float4 v = (i == 0) ? xq0 : xq1;
        float4 o;
        o.x = __fadd_rn(v.x, __fsub_rn(q.x, v.x));
        o.y = __fadd_rn(v.y, __fsub_rn(q.y, v.y));
        o.z = __fadd_rn(v.z, __fsub_rn(q.z, v.z));
        o.w = __fadd_rn(v.w, __fsub_rn(q.w, v.w));
        op4[lane + 32 * i] = o;
        double dx = (double)v.x - (double)q.x, dy = (double)v.y - (double)q.y;
        double dz = (double)v.z - (double)q.z, dw = (double)v.w - (double)q.w;
        accd += dx * dx + dy * dy + dz * dz + dw * dw;
    }
    #pragma unroll
    for (int off = 16; off > 0; off >>= 1)
        accd += __shfl_down_sync(0xffffffffu, accd, off);
    if (lane == 0) {
        atomicAdd(&g_partials[row & 255], accd);
        if (write_idx) out_idx[row] = (float)bidx;
    }
}

// ---------------------------------------------------------------------------
// Kernel D: finalize losses
// ---------------------------------------------------------------------------
__global__ void vq_final(float* __restrict__ out, long long nd, int has_extra) {
    __shared__ double sd[256];
    sd[threadIdx.x] = g_partials[threadIdx.x];
    __syncthreads();
    #pragma unroll
    for (int s = 128; s > 0; s >>= 1) {
        if (threadIdx.x < s) sd[threadIdx.x] += sd[threadIdx.x + s];
        __syncthreads();
    }
    if (threadIdx.x == 0 && has_extra) {
        float l = (float)(sd[0] / (double)nd);
        out[nd]     = l;
        out[nd + 1] = l;
    }
}

// ---------------------------------------------------------------------------
extern "C" void kernel_launch(void* const* d_in, const int* in_sizes, int n_in,
                              void* d_out, int out_size) {
    const float* x   = (const float*)d_in[0];
    const float* vec = (const float*)d_in[1];
    float* out = (float*)d_out;

    int n = in_sizes[0] / DDIM;                 // 65536 rows
    long long nd = (long long)n * DDIM;
    int has_extra = ((long long)out_size >= nd + 2 + n) ? 1 : 0;

    cudaFuncSetAttribute(vq_mma, cudaFuncAttributeMaxDynamicSharedMemorySize,
                         SM_MMA_BYTES);

    vq_prep<<<MAXN / 256, 256>>>(vec);
    vq_transpose<<<dim3(KDIM / 32, DDIM / 32), dim3(32, 8)>>>(vec);
    vq_mma<<<n / PM, 256, SM_MMA_BYTES>>>(x);
    vq_finish<<<n / 8, 256>>>(x, out, out + nd + 2, has_extra);
    vq_final<<<1, 256>>>(out, nd, has_extra);
}